// round 5
// baseline (speedup 1.0000x reference)
#include <cuda_runtime.h>

#define N 8192
#define NMAT ((size_t)N * (size_t)N)          // 67108864
#define OFF_MASKS (4 * N * 3)                 // 98304
#define OFF_ADJ   (OFF_MASKS + 4 * N)         // 131072

// Voxel grids: dims = ceil(30/v)+1
// L1: vs(0.5,0.5,1.0) -> (61,61,31)
// L2: vs(0.7,0.7,1.2) -> (44,44,26)
// L3: vs(0.9,0.9,1.4) -> (35,35,23)
#define NSEG1 (61 * 61 * 31)   // 115351
#define NSEG2 (44 * 44 * 26)   // 50336
#define NSEG3 (35 * 35 * 23)   // 28175
#define NSEG_TOT (NSEG1 + NSEG2 + NSEG3)

// Scratch zero-initialized at module load; k_reset (hidden under adjB)
// restores it for the next graph replay. g_first empty sentinel = 0
// (we store N - i > 0 and take max == N - min(i)).
__device__ float g_sx[NSEG_TOT];
__device__ float g_sy[NSEG_TOT];
__device__ float g_sz[NSEG_TOT];
__device__ float g_cn[NSEG_TOT];
__device__ int   g_first[NSEG_TOT];
__device__ float4 g_pts[4][N];   // (x,y,z,valid) per level

__constant__ int   c_la[6] = {0, 1, 2, 1, 2, 3};
__constant__ int   c_lb[6] = {1, 2, 3, 1, 2, 3};
__constant__ float c_r2[6] = {1.0f, 2.25f, 4.0f, 2.25f, 4.0f, 6.25f};
__constant__ int   c_matA[2] = {0, 3};        // need levels 0,1 only
__constant__ int   c_matB[4] = {1, 2, 4, 5};  // need levels 2,3

__device__ __forceinline__ int lin_index(int l, float x, float y, float z) {
    if (l == 0) {
        int ix = min(max((int)floorf(x / 0.5f), 0), 60);
        int iy = min(max((int)floorf(y / 0.5f), 0), 60);
        int iz = min(max((int)floorf(z / 1.0f), 0), 30);
        return (ix * 61 + iy) * 31 + iz;
    } else if (l == 1) {
        int ix = min(max((int)floorf(x / 0.7f), 0), 43);
        int iy = min(max((int)floorf(y / 0.7f), 0), 43);
        int iz = min(max((int)floorf(z / 1.2f), 0), 25);
        return NSEG1 + (ix * 44 + iy) * 26 + iz;
    } else {
        int ix = min(max((int)floorf(x / 0.9f), 0), 34);
        int iy = min(max((int)floorf(y / 0.9f), 0), 34);
        int iz = min(max((int)floorf(z / 1.4f), 0), 22);
        return NSEG1 + NSEG2 + (ix * 35 + iy) * 23 + iz;
    }
}

__device__ __forceinline__ void scatter_level(int l, int i, float x, float y, float z) {
    int lin = lin_index(l, x, y, z);
    atomicAdd(&g_sx[lin], x);
    atomicAdd(&g_sy[lin], y);
    atomicAdd(&g_sz[lin], z);
    atomicAdd(&g_cn[lin], 1.0f);
    atomicMax(&g_first[lin], N - i);
}

__device__ __forceinline__ void gather_level(int l, int i, float x, float y, float z,
                                             float* __restrict__ out) {
    int lin = lin_index(l, x, y, z);
    float c  = fmaxf(g_cn[lin], 1.0f);
    float rc = 1.0f / c;
    float cx = g_sx[lin] * rc;
    float cy = g_sy[lin] * rc;
    float cz = g_sz[lin] * rc;
    bool  m  = (g_first[lin] == N - i);
    float mf = m ? 1.0f : 0.0f;
    g_pts[l + 1][i] = make_float4(cx, cy, cz, mf);
    size_t co = (size_t)(l + 1) * (N * 3) + (size_t)i * 3;
    out[co + 0] = m ? cx : 0.0f;
    out[co + 1] = m ? cy : 0.0f;
    out[co + 2] = m ? cz : 0.0f;
    out[OFF_MASKS + (l + 1) * N + i] = mf;
}

__global__ void k_scatter1(const float* __restrict__ pts) {
    int i = blockIdx.x * blockDim.x + threadIdx.x;
    if (i >= N) return;
    scatter_level(0, i, pts[i * 4 + 0], pts[i * 4 + 1], pts[i * 4 + 2]);
}

__global__ void k_scatter23(const float* __restrict__ pts) {
    int i = blockIdx.x * blockDim.x + threadIdx.x;
    if (i >= N) return;
    float x = pts[i * 4 + 0], y = pts[i * 4 + 1], z = pts[i * 4 + 2];
    scatter_level(1, i, x, y, z);
    scatter_level(2, i, x, y, z);
}

// Level-0 prep + voxel level 1 gather.
__global__ void k_gather1(const float* __restrict__ pts, float* __restrict__ out) {
    int i = blockIdx.x * blockDim.x + threadIdx.x;
    if (i >= N) return;
    float x = pts[i * 4 + 0], y = pts[i * 4 + 1], z = pts[i * 4 + 2];
    g_pts[0][i] = make_float4(x, y, z, 1.0f);
    out[i * 3 + 0] = x;
    out[i * 3 + 1] = y;
    out[i * 3 + 2] = z;
    out[OFF_MASKS + i] = 1.0f;
    gather_level(0, i, x, y, z, out);
}

__global__ void k_gather23(const float* __restrict__ pts, float* __restrict__ out) {
    int i = blockIdx.x * blockDim.x + threadIdx.x;
    if (i >= N) return;
    float x = pts[i * 4 + 0], y = pts[i * 4 + 1], z = pts[i * 4 + 2];
    gather_level(1, i, x, y, z, out);
    gather_level(2, i, x, y, z, out);
}

__global__ void k_reset() {
    int i = blockIdx.x * blockDim.x + threadIdx.x;
    if (i < NSEG_TOT) {
        g_sx[i] = 0.0f; g_sy[i] = 0.0f; g_sz[i] = 0.0f; g_cn[i] = 0.0f;
        g_first[i] = 0;
    }
}

__device__ __forceinline__ float pairval(float4 a, float4 b, float r2) {
    float dx = a.x - b.x, dy = a.y - b.y, dz = a.z - b.z;
    float d2 = fmaf(dx, dx, fmaf(dy, dy, dz * dz));
    return (d2 <= r2) ? (a.w * b.w) : 0.0f;
}

// 16 (i) x 1024 (j) tile per 256-thread block; 4 j's per thread (float4 store).
// R1 configuration — measured ~87% of HBM spec, write-ceiling bound.
__device__ __forceinline__ void adj_tile(int mat, float* __restrict__ out) {
    __shared__ float4 sa[16];
    const int   la = c_la[mat];
    const int   lb = c_lb[mat];
    const float r2 = c_r2[mat];
    const bool  diag = (mat >= 3);

    const int i0 = blockIdx.y * 16;
    const int j0 = blockIdx.x * 1024;
    const int t  = threadIdx.x;

    if (t < 16) sa[t] = g_pts[la][i0 + t];
    __syncthreads();

    const int j = j0 + t * 4;
    const float4 b0 = g_pts[lb][j + 0];
    const float4 b1 = g_pts[lb][j + 1];
    const float4 b2 = g_pts[lb][j + 2];
    const float4 b3 = g_pts[lb][j + 3];

    float* obase = out + OFF_ADJ + (size_t)mat * NMAT + (size_t)j;

#pragma unroll
    for (int ii = 0; ii < 16; ii++) {
        float4 a = sa[ii];
        int gi = i0 + ii;
        float4 v;
        v.x = pairval(a, b0, r2);
        v.y = pairval(a, b1, r2);
        v.z = pairval(a, b2, r2);
        v.w = pairval(a, b3, r2);
        if (diag) {
            int d = gi - j;
            if ((unsigned)d < 4u) ((float*)&v)[d] = 0.0f;
        }
        *(float4*)(obase + (size_t)gi * N) = v;
    }
}

__global__ void __launch_bounds__(256) k_adjA(float* __restrict__ out) {
    adj_tile(c_matA[blockIdx.z], out);
}

__global__ void __launch_bounds__(256) k_adjB(float* __restrict__ out) {
    adj_tile(c_matB[blockIdx.z], out);
}

extern "C" void kernel_launch(void* const* d_in, const int* in_sizes, int n_in,
                              void* d_out, int out_size) {
    const float* pts = (const float*)d_in[0];
    float* out = (float*)d_out;

    // One-time side resources (resource init only; per-call work identical).
    static cudaStream_t s1 = nullptr;
    static cudaEvent_t  e_start = nullptr, e_g1 = nullptr,
                        e_23 = nullptr, e_reset = nullptr;
    if (s1 == nullptr) {
        cudaStreamCreateWithFlags(&s1, cudaStreamNonBlocking);
        cudaEventCreateWithFlags(&e_start, cudaEventDisableTiming);
        cudaEventCreateWithFlags(&e_g1,    cudaEventDisableTiming);
        cudaEventCreateWithFlags(&e_23,    cudaEventDisableTiming);
        cudaEventCreateWithFlags(&e_reset, cudaEventDisableTiming);
    }

    // Fork side branch at entry.
    cudaEventRecord(e_start, 0);
    cudaStreamWaitEvent(s1, e_start, 0);

    // Side branch: levels 2,3 pipeline (disjoint scratch ranges from level 1).
    k_scatter23<<<64, 128, 0, s1>>>(pts);
    k_gather23<<<64, 128, 0, s1>>>(pts, out);
    cudaEventRecord(e_23, s1);

    // Main branch: level 1 pipeline, then adj for mats needing only L0/L1.
    k_scatter1<<<64, 128>>>(pts);
    k_gather1<<<64, 128>>>(pts, out);
    cudaEventRecord(e_g1, 0);

    dim3 gridA(N / 1024, N / 16, 2);
    k_adjA<<<gridA, 256>>>(out);

    // Reset after both gathers have consumed the scratch; hides under adjA/adjB.
    cudaStreamWaitEvent(s1, e_g1, 0);
    k_reset<<<(NSEG_TOT + 255) / 256, 256, 0, s1>>>();
    cudaEventRecord(e_reset, s1);

    // adjB needs levels 2,3 (ready long before adjA finishes).
    cudaStreamWaitEvent(0, e_23, 0);
    dim3 gridB(N / 1024, N / 16, 4);
    k_adjB<<<gridB, 256>>>(out);

    // Join: graph end depends on reset branch too.
    cudaStreamWaitEvent(0, e_reset, 0);
}

// round 6
// speedup vs baseline: 1.0181x; 1.0181x over previous
#include <cuda_runtime.h>

#define N 8192
#define NMAT ((size_t)N * (size_t)N)          // 67108864
#define OFF_MASKS (4 * N * 3)                 // 98304
#define OFF_ADJ   (OFF_MASKS + 4 * N)         // 131072

// Voxel grids: dims = ceil(30/v)+1
// L1: vs(0.5,0.5,1.0) -> (61,61,31)
// L2: vs(0.7,0.7,1.2) -> (44,44,26)
// L3: vs(0.9,0.9,1.4) -> (35,35,23)
#define NSEG1 (61 * 61 * 31)   // 115351
#define NSEG2 (44 * 44 * 26)   // 50336
#define NSEG3 (35 * 35 * 23)   // 28175
#define NSEG_TOT (NSEG1 + NSEG2 + NSEG3)

#define FRONT_BLOCKS 64
#define FRONT_THREADS 128

// Scratch zero-initialized at module load; k_reset (hidden under adj)
// restores it for the next replay. g_first empty sentinel = 0
// (we store N - i > 0; max(N-i) == N - min(i)).
__device__ float g_sx[NSEG_TOT];
__device__ float g_sy[NSEG_TOT];
__device__ float g_sz[NSEG_TOT];
__device__ float g_cn[NSEG_TOT];
__device__ int   g_first[NSEG_TOT];
__device__ float4 g_pts[4][N];          // (x,y,z,valid) per level
__device__ unsigned int g_bar;          // monotonic grid barrier (never reset)

__constant__ int   c_la[6] = {0, 1, 2, 1, 2, 3};
__constant__ int   c_lb[6] = {1, 2, 3, 1, 2, 3};
__constant__ float c_r2[6] = {1.0f, 2.25f, 4.0f, 2.25f, 4.0f, 6.25f};

__device__ __forceinline__ int lin_index(int l, float x, float y, float z) {
    if (l == 0) {
        int ix = min(max((int)floorf(x / 0.5f), 0), 60);
        int iy = min(max((int)floorf(y / 0.5f), 0), 60);
        int iz = min(max((int)floorf(z / 1.0f), 0), 30);
        return (ix * 61 + iy) * 31 + iz;
    } else if (l == 1) {
        int ix = min(max((int)floorf(x / 0.7f), 0), 43);
        int iy = min(max((int)floorf(y / 0.7f), 0), 43);
        int iz = min(max((int)floorf(z / 1.2f), 0), 25);
        return NSEG1 + (ix * 44 + iy) * 26 + iz;
    } else {
        int ix = min(max((int)floorf(x / 0.9f), 0), 34);
        int iy = min(max((int)floorf(y / 0.9f), 0), 34);
        int iz = min(max((int)floorf(z / 1.4f), 0), 22);
        return NSEG1 + NSEG2 + (ix * 35 + iy) * 23 + iz;
    }
}

// Fused scatter + grid-barrier + gather. 64 blocks x 128 threads — all blocks
// co-resident (64 << 148 SMs), so the software barrier cannot deadlock.
// Barrier is monotonic-generation based: no reset needed across graph replays.
__global__ void __launch_bounds__(FRONT_THREADS) k_front(
        const float* __restrict__ pts, float* __restrict__ out) {
    const int i = blockIdx.x * FRONT_THREADS + threadIdx.x;   // exactly N threads
    const float x = pts[i * 4 + 0];
    const float y = pts[i * 4 + 1];
    const float z = pts[i * 4 + 2];

    int lin[3];
#pragma unroll
    for (int l = 0; l < 3; l++) lin[l] = lin_index(l, x, y, z);

    // ---- scatter (atomics -> L2) ----
#pragma unroll
    for (int l = 0; l < 3; l++) {
        atomicAdd(&g_sx[lin[l]], x);
        atomicAdd(&g_sy[lin[l]], y);
        atomicAdd(&g_sz[lin[l]], z);
        atomicAdd(&g_cn[lin[l]], 1.0f);
        atomicMax(&g_first[lin[l]], N - i);
    }

    // ---- grid-wide barrier ----
    __threadfence();
    __syncthreads();
    if (threadIdx.x == 0) {
        unsigned int old = atomicAdd(&g_bar, 1u);
        unsigned int target = (old / FRONT_BLOCKS + 1u) * FRONT_BLOCKS;
        while (*(volatile unsigned int*)&g_bar < target) { }
    }
    __syncthreads();
    __threadfence();

    // ---- gather: level 0 prep + 3 voxel levels ----
    g_pts[0][i] = make_float4(x, y, z, 1.0f);
    out[i * 3 + 0] = x;
    out[i * 3 + 1] = y;
    out[i * 3 + 2] = z;
    out[OFF_MASKS + i] = 1.0f;

#pragma unroll
    for (int l = 0; l < 3; l++) {
        float c  = fmaxf(g_cn[lin[l]], 1.0f);
        float rc = 1.0f / c;
        float cx = g_sx[lin[l]] * rc;
        float cy = g_sy[lin[l]] * rc;
        float cz = g_sz[lin[l]] * rc;
        bool  m  = (g_first[lin[l]] == N - i);
        float mf = m ? 1.0f : 0.0f;
        g_pts[l + 1][i] = make_float4(cx, cy, cz, mf);
        size_t co = (size_t)(l + 1) * (N * 3) + (size_t)i * 3;
        out[co + 0] = m ? cx : 0.0f;
        out[co + 1] = m ? cy : 0.0f;
        out[co + 2] = m ? cz : 0.0f;
        out[OFF_MASKS + (l + 1) * N + i] = mf;
    }
}

// Coalesced zeroing of all voxel scratch; runs on forked branch under k_adj.
__global__ void k_reset() {
    int i = blockIdx.x * blockDim.x + threadIdx.x;
    if (i < NSEG_TOT) {
        g_sx[i] = 0.0f; g_sy[i] = 0.0f; g_sz[i] = 0.0f; g_cn[i] = 0.0f;
        g_first[i] = 0;
    }
}

__device__ __forceinline__ float pairval(float4 a, float4 b, float r2) {
    float dx = a.x - b.x, dy = a.y - b.y, dz = a.z - b.z;
    float d2 = fmaf(dx, dx, fmaf(dy, dy, dz * dz));
    return (d2 <= r2) ? (a.w * b.w) : 0.0f;
}

// 16 (i) x 1024 (j) tile per 256-thread block; 4 j's per thread (float4 store).
// R1 configuration — measured ~87% of HBM spec, write-ceiling bound.
__global__ void __launch_bounds__(256) k_adj(float* __restrict__ out) {
    const int mat = blockIdx.z;
    __shared__ float4 sa[16];
    const int   la = c_la[mat];
    const int   lb = c_lb[mat];
    const float r2 = c_r2[mat];
    const bool  diag = (mat >= 3);

    const int i0 = blockIdx.y * 16;
    const int j0 = blockIdx.x * 1024;
    const int t  = threadIdx.x;

    if (t < 16) sa[t] = g_pts[la][i0 + t];
    __syncthreads();

    const int j = j0 + t * 4;
    const float4 b0 = g_pts[lb][j + 0];
    const float4 b1 = g_pts[lb][j + 1];
    const float4 b2 = g_pts[lb][j + 2];
    const float4 b3 = g_pts[lb][j + 3];

    float* obase = out + OFF_ADJ + (size_t)mat * NMAT + (size_t)j;

#pragma unroll
    for (int ii = 0; ii < 16; ii++) {
        float4 a = sa[ii];
        int gi = i0 + ii;
        float4 v;
        v.x = pairval(a, b0, r2);
        v.y = pairval(a, b1, r2);
        v.z = pairval(a, b2, r2);
        v.w = pairval(a, b3, r2);
        if (diag) {
            int d = gi - j;
            if ((unsigned)d < 4u) ((float*)&v)[d] = 0.0f;
        }
        *(float4*)(obase + (size_t)gi * N) = v;
    }
}

extern "C" void kernel_launch(void* const* d_in, const int* in_sizes, int n_in,
                              void* d_out, int out_size) {
    const float* pts = (const float*)d_in[0];
    float* out = (float*)d_out;

    // One-time side resources (resource init only; per-call work identical).
    static cudaStream_t s_side = nullptr;
    static cudaEvent_t  e_front = nullptr, e_reset = nullptr;
    if (s_side == nullptr) {
        cudaStreamCreateWithFlags(&s_side, cudaStreamNonBlocking);
        cudaEventCreateWithFlags(&e_front, cudaEventDisableTiming);
        cudaEventCreateWithFlags(&e_reset, cudaEventDisableTiming);
    }

    // Fused front: scatter + grid barrier + gather, one launch.
    k_front<<<FRONT_BLOCKS, FRONT_THREADS>>>(pts, out);
    cudaEventRecord(e_front, 0);

    // Fork: reset scratch concurrently with adj (disjoint data).
    cudaStreamWaitEvent(s_side, e_front, 0);
    k_reset<<<(NSEG_TOT + 255) / 256, 256, 0, s_side>>>();
    cudaEventRecord(e_reset, s_side);

    dim3 grid(N / 1024, N / 16, 6);
    k_adj<<<grid, 256>>>(out);

    // Join.
    cudaStreamWaitEvent(0, e_reset, 0);
}

// round 7
// speedup vs baseline: 1.0266x; 1.0084x over previous
#include <cuda_runtime.h>

#define N 8192
#define NMAT ((size_t)N * (size_t)N)          // 67108864
#define OFF_MASKS (4 * N * 3)                 // 98304
#define OFF_ADJ   (OFF_MASKS + 4 * N)         // 131072

// Voxel grids: dims = ceil(30/v)+1
// L1: vs(0.5,0.5,1.0) -> (61,61,31)
// L2: vs(0.7,0.7,1.2) -> (44,44,26)
// L3: vs(0.9,0.9,1.4) -> (35,35,23)
#define NSEG1 (61 * 61 * 31)   // 115351
#define NSEG2 (44 * 44 * 26)   // 50336
#define NSEG3 (35 * 35 * 23)   // 28175
#define NSEG_TOT (NSEG1 + NSEG2 + NSEG3)

#define FRONT_BLOCKS 128
#define FRONT_THREADS 192      // 128*192 = 24576 = N*3 (one thread per point-level)

// Scratch zero-initialized at module load; k_reset (hidden under adj)
// restores it for the next replay. g_first empty sentinel = 0
// (we store N - i > 0; max(N-i) == N - min(i)).
__device__ float g_sx[NSEG_TOT];
__device__ float g_sy[NSEG_TOT];
__device__ float g_sz[NSEG_TOT];
__device__ float g_cn[NSEG_TOT];
__device__ int   g_first[NSEG_TOT];
__device__ float4 g_pts[4][N];          // (x,y,z,valid) per level
__device__ unsigned int g_bar;          // monotonic grid barrier (never reset)

__constant__ int   c_la[6] = {0, 1, 2, 1, 2, 3};
__constant__ int   c_lb[6] = {1, 2, 3, 1, 2, 3};
__constant__ float c_r2[6] = {1.0f, 2.25f, 4.0f, 2.25f, 4.0f, 6.25f};

__device__ __forceinline__ int lin_index(int l, float x, float y, float z) {
    if (l == 0) {
        int ix = min(max((int)floorf(x / 0.5f), 0), 60);
        int iy = min(max((int)floorf(y / 0.5f), 0), 60);
        int iz = min(max((int)floorf(z / 1.0f), 0), 30);
        return (ix * 61 + iy) * 31 + iz;
    } else if (l == 1) {
        int ix = min(max((int)floorf(x / 0.7f), 0), 43);
        int iy = min(max((int)floorf(y / 0.7f), 0), 43);
        int iz = min(max((int)floorf(z / 1.2f), 0), 25);
        return NSEG1 + (ix * 44 + iy) * 26 + iz;
    } else {
        int ix = min(max((int)floorf(x / 0.9f), 0), 34);
        int iy = min(max((int)floorf(y / 0.9f), 0), 34);
        int iz = min(max((int)floorf(z / 1.4f), 0), 22);
        return NSEG1 + NSEG2 + (ix * 35 + iy) * 23 + iz;
    }
}

// Fused scatter + grid-barrier + gather, ONE thread per (point, level) pair:
// 24576 threads (3x the R6 parallelism, 1/3 the per-thread latency chain).
// 128 blocks <= 148 SMs: all co-resident, so the software barrier is safe.
// Barrier is monotonic-generation based: no reset needed across graph replays.
__global__ void __launch_bounds__(FRONT_THREADS) k_front(
        const float* __restrict__ pts, float* __restrict__ out) {
    const int g = blockIdx.x * FRONT_THREADS + threadIdx.x;   // 0..24575
    const int l = g >> 13;          // level 0..2 (warp-uniform)
    const int i = g & (N - 1);      // point 0..8191 (consecutive in warp)

    const float x = pts[i * 4 + 0];
    const float y = pts[i * 4 + 1];
    const float z = pts[i * 4 + 2];
    const int lin = lin_index(l, x, y, z);

    // ---- scatter (5 independent L2 red/atomics) ----
    atomicAdd(&g_sx[lin], x);
    atomicAdd(&g_sy[lin], y);
    atomicAdd(&g_sz[lin], z);
    atomicAdd(&g_cn[lin], 1.0f);
    atomicMax(&g_first[lin], N - i);

    // ---- grid-wide barrier ----
    __threadfence();
    __syncthreads();
    if (threadIdx.x == 0) {
        unsigned int old = atomicAdd(&g_bar, 1u);
        unsigned int target = (old / FRONT_BLOCKS + 1u) * FRONT_BLOCKS;
        while (*(volatile unsigned int*)&g_bar < target) { }
    }
    __syncthreads();
    __threadfence();

    // ---- gather for this (point, level) ----
    float c  = fmaxf(g_cn[lin], 1.0f);
    float rc = 1.0f / c;
    float cx = g_sx[lin] * rc;
    float cy = g_sy[lin] * rc;
    float cz = g_sz[lin] * rc;
    bool  m  = (g_first[lin] == N - i);
    float mf = m ? 1.0f : 0.0f;
    g_pts[l + 1][i] = make_float4(cx, cy, cz, mf);
    size_t co = (size_t)(l + 1) * (N * 3) + (size_t)i * 3;
    out[co + 0] = m ? cx : 0.0f;
    out[co + 1] = m ? cy : 0.0f;
    out[co + 2] = m ? cz : 0.0f;
    out[OFF_MASKS + (l + 1) * N + i] = mf;

    // Level-0 prep handled by the l==0 third of threads.
    if (l == 0) {
        g_pts[0][i] = make_float4(x, y, z, 1.0f);
        out[i * 3 + 0] = x;
        out[i * 3 + 1] = y;
        out[i * 3 + 2] = z;
        out[OFF_MASKS + i] = 1.0f;
    }
}

// Coalesced zeroing of all voxel scratch; runs on forked branch under k_adj.
__global__ void k_reset() {
    int i = blockIdx.x * blockDim.x + threadIdx.x;
    if (i < NSEG_TOT) {
        g_sx[i] = 0.0f; g_sy[i] = 0.0f; g_sz[i] = 0.0f; g_cn[i] = 0.0f;
        g_first[i] = 0;
    }
}

__device__ __forceinline__ float pairval(float4 a, float4 b, float r2) {
    float dx = a.x - b.x, dy = a.y - b.y, dz = a.z - b.z;
    float d2 = fmaf(dx, dx, fmaf(dy, dy, dz * dz));
    return (d2 <= r2) ? (a.w * b.w) : 0.0f;
}

// 16 (i) x 1024 (j) tile per 256-thread block; 4 j's per thread (float4 store).
// R1 configuration — measured ~87% of HBM spec, write-ceiling bound.
__global__ void __launch_bounds__(256) k_adj(float* __restrict__ out) {
    const int mat = blockIdx.z;
    __shared__ float4 sa[16];
    const int   la = c_la[mat];
    const int   lb = c_lb[mat];
    const float r2 = c_r2[mat];
    const bool  diag = (mat >= 3);

    const int i0 = blockIdx.y * 16;
    const int j0 = blockIdx.x * 1024;
    const int t  = threadIdx.x;

    if (t < 16) sa[t] = g_pts[la][i0 + t];
    __syncthreads();

    const int j = j0 + t * 4;
    const float4 b0 = g_pts[lb][j + 0];
    const float4 b1 = g_pts[lb][j + 1];
    const float4 b2 = g_pts[lb][j + 2];
    const float4 b3 = g_pts[lb][j + 3];

    float* obase = out + OFF_ADJ + (size_t)mat * NMAT + (size_t)j;

#pragma unroll
    for (int ii = 0; ii < 16; ii++) {
        float4 a = sa[ii];
        int gi = i0 + ii;
        float4 v;
        v.x = pairval(a, b0, r2);
        v.y = pairval(a, b1, r2);
        v.z = pairval(a, b2, r2);
        v.w = pairval(a, b3, r2);
        if (diag) {
            int d = gi - j;
            if ((unsigned)d < 4u) ((float*)&v)[d] = 0.0f;
        }
        *(float4*)(obase + (size_t)gi * N) = v;
    }
}

extern "C" void kernel_launch(void* const* d_in, const int* in_sizes, int n_in,
                              void* d_out, int out_size) {
    const float* pts = (const float*)d_in[0];
    float* out = (float*)d_out;

    // One-time side resources (resource init only; per-call work identical).
    static cudaStream_t s_side = nullptr;
    static cudaEvent_t  e_front = nullptr, e_reset = nullptr;
    if (s_side == nullptr) {
        cudaStreamCreateWithFlags(&s_side, cudaStreamNonBlocking);
        cudaEventCreateWithFlags(&e_front, cudaEventDisableTiming);
        cudaEventCreateWithFlags(&e_reset, cudaEventDisableTiming);
    }

    // Fused front: scatter + grid barrier + gather, one launch.
    k_front<<<FRONT_BLOCKS, FRONT_THREADS>>>(pts, out);
    cudaEventRecord(e_front, 0);

    // Fork: reset scratch concurrently with adj (disjoint data).
    cudaStreamWaitEvent(s_side, e_front, 0);
    k_reset<<<(NSEG_TOT + 255) / 256, 256, 0, s_side>>>();
    cudaEventRecord(e_reset, s_side);

    dim3 grid(N / 1024, N / 16, 6);
    k_adj<<<grid, 256>>>(out);

    // Join.
    cudaStreamWaitEvent(0, e_reset, 0);
}